// round 2
// baseline (speedup 1.0000x reference)
#include <cuda_runtime.h>
#include <cstdint>

#define N_NODES 50000
#define N_EDGES 800000
#define IN_DIM  256
#define OUT_DIM 64
#define NEG_SLOPE 0.01f
#define TILE_M 128

typedef unsigned long long ull;

// ---------------- device scratch ----------------
__device__ float g_z[N_NODES * OUT_DIM];     // 12.8 MB, L2-resident
__device__ float g_sl[N_NODES];
__device__ float g_sr[N_NODES];
__device__ int   g_off[N_NODES + 1];         // CSR offsets (by dst)
__device__ int   g_cur[N_NODES];             // scatter cursors
__device__ int   g_ssrc[N_EDGES];            // src ids sorted by dst
__device__ float g_se[N_EDGES];              // leaky(e) sorted by dst

// ---------------- GEMM: z = h @ W ----------------
// 256 threads, TILE_M=128 rows. Thread tile: 8 row-pairs x 2 cols (32 f32x2 accs).
// Also zeroes g_off for the later histogram (fused to drop a launch).
__global__ void gemm_kernel(const float* __restrict__ h,
                            const float* __restrict__ W) {
    extern __shared__ float smem[];
    float*  Wsh = smem;                                 // [256][64]
    float2* hp  = (float2*)(smem + IN_DIM * OUT_DIM);   // [64 pairs][256 k]

    const int t    = threadIdx.x;
    const int row0 = blockIdx.x * TILE_M;

    // fused: zero histogram buffer (grid covers 50001 elements)
    for (int i = blockIdx.x * 256 + t; i <= N_NODES; i += gridDim.x * 256)
        g_off[i] = 0;

    // load W (coalesced, 64KB)
    #pragma unroll 4
    for (int i = t; i < IN_DIM * OUT_DIM; i += 256) Wsh[i] = W[i];

    // load h tile row-paired: hp[p][k] = (h[2p][k], h[2p+1][k])
    for (int i = t; i < TILE_M * (IN_DIM / 4); i += 256) {
        int r  = i / (IN_DIM / 4);
        int k4 = i % (IN_DIM / 4);
        int gr = row0 + r;
        float4 v = (gr < N_NODES) ? ((const float4*)h)[gr * (IN_DIM / 4) + k4]
                                  : make_float4(0.f, 0.f, 0.f, 0.f);
        int p = r >> 1, half = r & 1;
        float* dst = (float*)&hp[p * IN_DIM + k4 * 4];
        dst[0 * 2 + half] = v.x;
        dst[1 * 2 + half] = v.y;
        dst[2 * 2 + half] = v.z;
        dst[3 * 2 + half] = v.w;
    }
    __syncthreads();

    const int c0  = (t & 31) * 2;        // column pair {c0, c0+1}
    const int pr0 = (t >> 5) * 8;        // 8 row-pairs per thread

    ull acc[8][2];
    #pragma unroll
    for (int p = 0; p < 8; p++) { acc[p][0] = 0ULL; acc[p][1] = 0ULL; }

    #pragma unroll 2
    for (int k0 = 0; k0 < IN_DIM; k0 += 2) {
        float2 wA = *(const float2*)&Wsh[k0 * OUT_DIM + c0];        // (w(k0,c0), w(k0,c1))
        float2 wB = *(const float2*)&Wsh[(k0 + 1) * OUT_DIM + c0];
        ull b00, b01, b10, b11;
        asm("mov.b64 %0, {%1, %1};" : "=l"(b00) : "r"(__float_as_uint(wA.x)));
        asm("mov.b64 %0, {%1, %1};" : "=l"(b01) : "r"(__float_as_uint(wA.y)));
        asm("mov.b64 %0, {%1, %1};" : "=l"(b10) : "r"(__float_as_uint(wB.x)));
        asm("mov.b64 %0, {%1, %1};" : "=l"(b11) : "r"(__float_as_uint(wB.y)));
        #pragma unroll
        for (int p = 0; p < 8; p++) {
            ulonglong2 vv = *(const ulonglong2*)&hp[(pr0 + p) * IN_DIM + k0];
            asm("fma.rn.f32x2 %0, %1, %2, %0;" : "+l"(acc[p][0]) : "l"(vv.x), "l"(b00));
            asm("fma.rn.f32x2 %0, %1, %2, %0;" : "+l"(acc[p][1]) : "l"(vv.x), "l"(b01));
            asm("fma.rn.f32x2 %0, %1, %2, %0;" : "+l"(acc[p][0]) : "l"(vv.y), "l"(b10));
            asm("fma.rn.f32x2 %0, %1, %2, %0;" : "+l"(acc[p][1]) : "l"(vv.y), "l"(b11));
        }
    }

    #pragma unroll
    for (int p = 0; p < 8; p++) {
        int r0 = row0 + 2 * (pr0 + p);
        float2 a0 = *(float2*)&acc[p][0];   // (z[r0][c0], z[r0+1][c0])
        float2 a1 = *(float2*)&acc[p][1];   // (z[r0][c1], z[r0+1][c1])
        if (r0 < N_NODES)     *(float2*)&g_z[r0 * OUT_DIM + c0]       = make_float2(a0.x, a1.x);
        if (r0 + 1 < N_NODES) *(float2*)&g_z[(r0 + 1) * OUT_DIM + c0] = make_float2(a0.y, a1.y);
    }
}

// ---------------- s_l / s_r per node + fused edge histogram ----------------
__global__ void s_kernel(const float* __restrict__ a_attn,
                         const int* __restrict__ edge_dst) {
    int gt   = blockIdx.x * blockDim.x + threadIdx.x;
    // fused histogram: one edge per thread (grid is 1.6M threads > 800k edges)
    if (gt < N_EDGES) atomicAdd(&g_off[edge_dst[gt] + 1], 1);

    int gw   = gt >> 5;
    int lane = threadIdx.x & 31;
    if (gw >= N_NODES) return;
    float2 zv = *(const float2*)&g_z[gw * OUT_DIM + 2 * lane];
    float al0 = a_attn[2 * lane],      al1 = a_attn[2 * lane + 1];
    float ar0 = a_attn[64 + 2 * lane], ar1 = a_attn[64 + 2 * lane + 1];
    float sl = zv.x * al0 + zv.y * al1;
    float sr = zv.x * ar0 + zv.y * ar1;
    #pragma unroll
    for (int o = 16; o; o >>= 1) {
        sl += __shfl_xor_sync(0xffffffffu, sl, o);
        sr += __shfl_xor_sync(0xffffffffu, sr, o);
    }
    if (lane == 0) { g_sl[gw] = sl; g_sr[gw] = sr; }
}

// ---------------- thread-coarsened single-block scan ----------------
// 1024 threads x 49 contiguous counts each (covers 50176 >= 50000).
__global__ void scan_kernel() {
    const int C = 49;
    __shared__ int wsum[32];
    const int t = threadIdx.x, lane = t & 31, w = t >> 5;
    const int base = 1 + t * C;

    // phase 1: local sum
    int s = 0;
    #pragma unroll
    for (int i = 0; i < C; i++) {
        int idx = base + i;
        s += (idx <= N_NODES) ? g_off[idx] : 0;
    }
    // block-level exclusive scan of s
    int x = s;
    #pragma unroll
    for (int o = 1; o < 32; o <<= 1) {
        int y = __shfl_up_sync(0xffffffffu, x, o);
        if (lane >= o) x += y;
    }
    if (lane == 31) wsum[w] = x;
    __syncthreads();
    if (w == 0) {
        int v = wsum[lane];
        #pragma unroll
        for (int o = 1; o < 32; o <<= 1) {
            int y = __shfl_up_sync(0xffffffffu, v, o);
            if (lane >= o) v += y;
        }
        wsum[lane] = v;
    }
    __syncthreads();
    int run = x - s + ((w > 0) ? wsum[w - 1] : 0);   // exclusive base for this thread

    // phase 2: write inclusive offsets + cursors (each thread owns its range)
    #pragma unroll
    for (int i = 0; i < C; i++) {
        int idx = base + i;
        if (idx <= N_NODES) {
            int cnt = g_off[idx];
            g_cur[idx - 1] = run;
            run += cnt;
            g_off[idx] = run;
        }
    }
}

// ---------------- scatter edges into CSR order ----------------
__global__ void scatter_kernel(const int* __restrict__ edge_src,
                               const int* __restrict__ edge_dst) {
    int i = blockIdx.x * blockDim.x + threadIdx.x;
    if (i >= N_EDGES) return;
    int s = edge_src[i];
    int d = edge_dst[i];
    float e = g_sl[s] + g_sr[d];
    e = (e > 0.f) ? e : NEG_SLOPE * e;
    int pos = atomicAdd(&g_cur[d], 1);
    g_ssrc[pos] = s;
    g_se[pos]   = e;
}

// ---------------- node phase: one warp per dst node ----------------
__global__ void node_kernel(float* __restrict__ out) {
    int gw   = (blockIdx.x * blockDim.x + threadIdx.x) >> 5;
    int lane = threadIdx.x & 31;
    if (gw >= N_NODES) return;
    int beg = g_off[gw];
    int end = g_off[gw + 1];

    float2 acc = make_float2(0.f, 0.f);
    if (beg < end) {
        float m = -__int_as_float(0x7f800000);
        for (int j = beg + lane; j < end; j += 32) m = fmaxf(m, g_se[j]);
        #pragma unroll
        for (int o = 16; o; o >>= 1) m = fmaxf(m, __shfl_xor_sync(0xffffffffu, m, o));
        float den = 0.f;
        for (int j = beg + lane; j < end; j += 32) den += __expf(g_se[j] - m);
        #pragma unroll
        for (int o = 16; o; o >>= 1) den += __shfl_xor_sync(0xffffffffu, den, o);
        float invden = 1.0f / den;

        // weighted gather, unrolled x2 for MLP on the ssrc -> z-row chain
        int j = beg;
        for (; j + 1 < end; j += 2) {
            int   s0 = g_ssrc[j],   s1 = g_ssrc[j + 1];
            float e0 = g_se[j],     e1 = g_se[j + 1];
            float2 z0 = *(const float2*)&g_z[s0 * OUT_DIM + 2 * lane];
            float2 z1 = *(const float2*)&g_z[s1 * OUT_DIM + 2 * lane];
            float a0 = __expf(e0 - m) * invden;
            float a1 = __expf(e1 - m) * invden;
            acc.x += a0 * z0.x + a1 * z1.x;
            acc.y += a0 * z0.y + a1 * z1.y;
        }
        if (j < end) {
            int   s0 = g_ssrc[j];
            float a0 = __expf(g_se[j] - m) * invden;
            float2 z0 = *(const float2*)&g_z[s0 * OUT_DIM + 2 * lane];
            acc.x += a0 * z0.x;
            acc.y += a0 * z0.y;
        }
    }
    *(float2*)&out[gw * OUT_DIM + 2 * lane] = acc;
}

// ---------------- launch ----------------
extern "C" void kernel_launch(void* const* d_in, const int* in_sizes, int n_in,
                              void* d_out, int out_size) {
    const float* h        = (const float*)d_in[0];
    const int*   edge_src = (const int*)d_in[1];
    const int*   edge_dst = (const int*)d_in[2];
    const float* W_fc     = (const float*)d_in[3];
    const float* a_attn   = (const float*)d_in[4];
    float* out = (float*)d_out;

    const int SMEM = (IN_DIM * OUT_DIM) * 4 + (TILE_M / 2) * IN_DIM * 8; // 64KB + 128KB
    cudaFuncSetAttribute(gemm_kernel, cudaFuncAttributeMaxDynamicSharedMemorySize, SMEM);

    gemm_kernel<<<(N_NODES + TILE_M - 1) / TILE_M, 256, SMEM>>>(h, W_fc);
    s_kernel<<<(N_NODES * 32 + 255) / 256, 256>>>(a_attn, edge_dst);
    scan_kernel<<<1, 1024>>>();
    scatter_kernel<<<(N_EDGES + 255) / 256, 256>>>(edge_src, edge_dst);
    node_kernel<<<(N_NODES * 32 + 255) / 256, 256>>>(out);
}

// round 5
// speedup vs baseline: 1.0107x; 1.0107x over previous
#include <cuda_runtime.h>
#include <cstdint>

#define N_NODES 50000
#define N_EDGES 800000
#define IN_DIM  256
#define OUT_DIM 64
#define NEG_SLOPE 0.01f
#define TILE_M 128

typedef unsigned long long ull;

// ---------------- device scratch ----------------
__device__ float g_z[N_NODES * OUT_DIM];     // 12.8 MB, L2-resident
__device__ float g_sl[N_NODES];
__device__ float g_sr[N_NODES];
__device__ float g_den[N_NODES];             // softmax denominators (atomic)
__device__ int   g_off[N_NODES + 1];         // CSR offsets (by dst)
__device__ int   g_cur[N_NODES];             // scatter cursors
__device__ ull   g_ep[N_EDGES];              // packed (exp(e)<<32 | src), dst-sorted

// ---------------- GEMM: z = h @ W (PROVEN in R2) ----------------
// 256 threads, TILE_M=128 rows. Thread tile: 8 row-pairs x 2 cols.
__global__ void gemm_kernel(const float* __restrict__ h,
                            const float* __restrict__ W) {
    extern __shared__ float smem[];
    float*  Wsh = smem;                                 // [256][64]
    float2* hp  = (float2*)(smem + IN_DIM * OUT_DIM);   // [64 pairs][256 k]

    const int t    = threadIdx.x;
    const int row0 = blockIdx.x * TILE_M;

    #pragma unroll 4
    for (int i = t; i < IN_DIM * OUT_DIM; i += 256) Wsh[i] = W[i];

    for (int i = t; i < TILE_M * (IN_DIM / 4); i += 256) {
        int r  = i / (IN_DIM / 4);
        int k4 = i % (IN_DIM / 4);
        int gr = row0 + r;
        float4 v = (gr < N_NODES) ? ((const float4*)h)[gr * (IN_DIM / 4) + k4]
                                  : make_float4(0.f, 0.f, 0.f, 0.f);
        int p = r >> 1, half = r & 1;
        float* dst = (float*)&hp[p * IN_DIM + k4 * 4];
        dst[0 * 2 + half] = v.x;
        dst[1 * 2 + half] = v.y;
        dst[2 * 2 + half] = v.z;
        dst[3 * 2 + half] = v.w;
    }
    __syncthreads();

    const int c0  = (t & 31) * 2;
    const int pr0 = (t >> 5) * 8;

    ull acc[8][2];
    #pragma unroll
    for (int p = 0; p < 8; p++) { acc[p][0] = 0ULL; acc[p][1] = 0ULL; }

    #pragma unroll 2
    for (int k0 = 0; k0 < IN_DIM; k0 += 2) {
        float2 wA = *(const float2*)&Wsh[k0 * OUT_DIM + c0];
        float2 wB = *(const float2*)&Wsh[(k0 + 1) * OUT_DIM + c0];
        ull b00, b01, b10, b11;
        asm("mov.b64 %0, {%1, %1};" : "=l"(b00) : "r"(__float_as_uint(wA.x)));
        asm("mov.b64 %0, {%1, %1};" : "=l"(b01) : "r"(__float_as_uint(wA.y)));
        asm("mov.b64 %0, {%1, %1};" : "=l"(b10) : "r"(__float_as_uint(wB.x)));
        asm("mov.b64 %0, {%1, %1};" : "=l"(b11) : "r"(__float_as_uint(wB.y)));
        #pragma unroll
        for (int p = 0; p < 8; p++) {
            ulonglong2 vv = *(const ulonglong2*)&hp[(pr0 + p) * IN_DIM + k0];
            asm("fma.rn.f32x2 %0, %1, %2, %0;" : "+l"(acc[p][0]) : "l"(vv.x), "l"(b00));
            asm("fma.rn.f32x2 %0, %1, %2, %0;" : "+l"(acc[p][1]) : "l"(vv.x), "l"(b01));
            asm("fma.rn.f32x2 %0, %1, %2, %0;" : "+l"(acc[p][0]) : "l"(vv.y), "l"(b10));
            asm("fma.rn.f32x2 %0, %1, %2, %0;" : "+l"(acc[p][1]) : "l"(vv.y), "l"(b11));
        }
    }

    #pragma unroll
    for (int p = 0; p < 8; p++) {
        int r0 = row0 + 2 * (pr0 + p);
        float2 a0 = *(float2*)&acc[p][0];
        float2 a1 = *(float2*)&acc[p][1];
        if (r0 < N_NODES)     *(float2*)&g_z[r0 * OUT_DIM + c0]       = make_float2(a0.x, a1.x);
        if (r0 + 1 < N_NODES) *(float2*)&g_z[(r0 + 1) * OUT_DIM + c0] = make_float2(a0.y, a1.y);
    }
}

// ---------------- s_l / s_r per node (PROVEN in R1) ----------------
__global__ void s_kernel(const float* __restrict__ a_attn) {
    int gw   = (blockIdx.x * blockDim.x + threadIdx.x) >> 5;
    int lane = threadIdx.x & 31;
    if (gw >= N_NODES) return;
    float2 zv = *(const float2*)&g_z[gw * OUT_DIM + 2 * lane];
    float al0 = a_attn[2 * lane],      al1 = a_attn[2 * lane + 1];
    float ar0 = a_attn[64 + 2 * lane], ar1 = a_attn[64 + 2 * lane + 1];
    float sl = zv.x * al0 + zv.y * al1;
    float sr = zv.x * ar0 + zv.y * ar1;
    #pragma unroll
    for (int o = 16; o; o >>= 1) {
        sl += __shfl_xor_sync(0xffffffffu, sl, o);
        sr += __shfl_xor_sync(0xffffffffu, sr, o);
    }
    if (lane == 0) { g_sl[gw] = sl; g_sr[gw] = sr; }
}

// ---------------- zero histogram + denominators ----------------
__global__ void zero_kernel() {
    int i = blockIdx.x * blockDim.x + threadIdx.x;
    if (i <= N_NODES) g_off[i] = 0;
    if (i < N_NODES)  g_den[i] = 0.f;
}

// ---------------- histogram (4 edges/thread for MLP) ----------------
__global__ void hist_kernel(const int* __restrict__ edge_dst) {
    int i = blockIdx.x * blockDim.x + threadIdx.x;
    if (i * 4 >= N_EDGES) return;
    int4 d = ((const int4*)edge_dst)[i];
    atomicAdd(&g_off[d.x + 1], 1);
    atomicAdd(&g_off[d.y + 1], 1);
    atomicAdd(&g_off[d.z + 1], 1);
    atomicAdd(&g_off[d.w + 1], 1);
}

// ---------------- thread-coarsened single-block scan (PROVEN in R2) ----------------
__global__ void scan_kernel() {
    const int C = 49;
    __shared__ int wsum[32];
    const int t = threadIdx.x, lane = t & 31, w = t >> 5;
    const int base = 1 + t * C;
    int s = 0;
    #pragma unroll
    for (int i = 0; i < C; i++) {
        int idx = base + i;
        s += (idx <= N_NODES) ? g_off[idx] : 0;
    }
    int x = s;
    #pragma unroll
    for (int o = 1; o < 32; o <<= 1) {
        int y = __shfl_up_sync(0xffffffffu, x, o);
        if (lane >= o) x += y;
    }
    if (lane == 31) wsum[w] = x;
    __syncthreads();
    if (w == 0) {
        int v = wsum[lane];
        #pragma unroll
        for (int o = 1; o < 32; o <<= 1) {
            int y = __shfl_up_sync(0xffffffffu, v, o);
            if (lane >= o) v += y;
        }
        wsum[lane] = v;
    }
    __syncthreads();
    int run = x - s + ((w > 0) ? wsum[w - 1] : 0);
    #pragma unroll
    for (int i = 0; i < C; i++) {
        int idx = base + i;
        if (idx <= N_NODES) {
            int cnt = g_off[idx];
            g_cur[idx - 1] = run;
            run += cnt;
            g_off[idx] = run;
        }
    }
}

// ---------------- scatter: packed exp(e)|src + denominator atomics ----------------
// No max subtraction: exp(e)/sum(exp(e)) == exp(e-m)/sum(exp(e-m)); e ~ N(0,1).
__global__ void scatter_kernel(const int* __restrict__ edge_src,
                               const int* __restrict__ edge_dst) {
    int i = blockIdx.x * blockDim.x + threadIdx.x;
    if (i * 2 >= N_EDGES) return;
    int2 s2 = ((const int2*)edge_src)[i];
    int2 d2 = ((const int2*)edge_dst)[i];
    float sl0 = g_sl[s2.x], sl1 = g_sl[s2.y];
    float sr0 = g_sr[d2.x], sr1 = g_sr[d2.y];
    float e0 = sl0 + sr0; e0 = (e0 > 0.f) ? e0 : NEG_SLOPE * e0;
    float e1 = sl1 + sr1; e1 = (e1 > 0.f) ? e1 : NEG_SLOPE * e1;
    float x0 = __expf(e0);
    float x1 = __expf(e1);
    int p0 = atomicAdd(&g_cur[d2.x], 1);
    int p1 = atomicAdd(&g_cur[d2.y], 1);
    g_ep[p0] = ((ull)__float_as_uint(x0) << 32) | (unsigned)s2.x;
    g_ep[p1] = ((ull)__float_as_uint(x1) << 32) | (unsigned)s2.y;
    atomicAdd(&g_den[d2.x], x0);
    atomicAdd(&g_den[d2.y], x1);
}

// ---------------- node phase: one warp per dst, SINGLE pass ----------------
__global__ void node_kernel(float* __restrict__ out) {
    int gw   = (blockIdx.x * blockDim.x + threadIdx.x) >> 5;
    int lane = threadIdx.x & 31;
    if (gw >= N_NODES) return;
    int beg = g_off[gw];
    int end = g_off[gw + 1];

    float2 acc = make_float2(0.f, 0.f);
    if (beg < end) {
        float invden = 1.0f / g_den[gw];
        int j = beg;
        for (; j + 1 < end; j += 2) {
            ull v0 = g_ep[j], v1 = g_ep[j + 1];
            int s0 = (int)(v0 & 0xffffffffu), s1 = (int)(v1 & 0xffffffffu);
            float2 z0 = *(const float2*)&g_z[s0 * OUT_DIM + 2 * lane];
            float2 z1 = *(const float2*)&g_z[s1 * OUT_DIM + 2 * lane];
            float a0 = __uint_as_float((uint32_t)(v0 >> 32)) * invden;
            float a1 = __uint_as_float((uint32_t)(v1 >> 32)) * invden;
            acc.x += a0 * z0.x + a1 * z1.x;
            acc.y += a0 * z0.y + a1 * z1.y;
        }
        if (j < end) {
            ull v0 = g_ep[j];
            int s0 = (int)(v0 & 0xffffffffu);
            float a0 = __uint_as_float((uint32_t)(v0 >> 32)) * invden;
            float2 z0 = *(const float2*)&g_z[s0 * OUT_DIM + 2 * lane];
            acc.x += a0 * z0.x;
            acc.y += a0 * z0.y;
        }
    }
    *(float2*)&out[gw * OUT_DIM + 2 * lane] = acc;
}

// ---------------- launch ----------------
extern "C" void kernel_launch(void* const* d_in, const int* in_sizes, int n_in,
                              void* d_out, int out_size) {
    const float* h        = (const float*)d_in[0];
    const int*   edge_src = (const int*)d_in[1];
    const int*   edge_dst = (const int*)d_in[2];
    const float* W_fc     = (const float*)d_in[3];
    const float* a_attn   = (const float*)d_in[4];
    float* out = (float*)d_out;

    const int SMEM = (IN_DIM * OUT_DIM) * 4 + (TILE_M / 2) * IN_DIM * 8; // 64KB + 128KB
    cudaFuncSetAttribute(gemm_kernel, cudaFuncAttributeMaxDynamicSharedMemorySize, SMEM);

    gemm_kernel<<<(N_NODES + TILE_M - 1) / TILE_M, 256, SMEM>>>(h, W_fc);
    s_kernel<<<(N_NODES * 32 + 255) / 256, 256>>>(a_attn);
    zero_kernel<<<(N_NODES + 256) / 256, 256>>>();
    hist_kernel<<<(N_EDGES / 4 + 255) / 256, 256>>>(edge_dst);
    scan_kernel<<<1, 1024>>>();
    scatter_kernel<<<(N_EDGES / 2 + 255) / 256, 256>>>(edge_src, edge_dst);
    node_kernel<<<(N_NODES * 32 + 255) / 256, 256>>>(out);
}

// round 6
// speedup vs baseline: 1.1745x; 1.1620x over previous
#include <cuda_runtime.h>
#include <cstdint>

#define N_NODES 50000
#define N_EDGES 800000
#define IN_DIM  256
#define OUT_DIM 64
#define NEG_SLOPE 0.01f
#define TILE_M 128

typedef unsigned long long ull;

// ---------------- device scratch ----------------
__device__ float g_z[N_NODES * OUT_DIM];     // 12.8 MB, L2-resident
__device__ float g_sl[N_NODES];
__device__ float g_sr[N_NODES];
__device__ float g_den[N_NODES];             // softmax denominators (atomic)
__device__ int   g_off[N_NODES + 1];         // CSR offsets (by dst)
__device__ int   g_cur[N_NODES];             // scatter cursors
__device__ ull   g_ep[N_EDGES];              // packed (exp(e)<<32 | src), dst-sorted

#define ADD2(a, b) asm("add.rn.f32x2 %0, %1, %2;" : "=l"(a) : "l"(a), "l"(b))

// ---------------- GEMM: z = h @ W + fused s_l/s_r (R2 core, proven) ----------------
__global__ void gemm_kernel(const float* __restrict__ h,
                            const float* __restrict__ W,
                            const float* __restrict__ a_attn) {
    extern __shared__ float smem[];
    float*  Wsh = smem;                                 // [256][64]
    float2* hp  = (float2*)(smem + IN_DIM * OUT_DIM);   // [64 pairs][256 k]

    const int t    = threadIdx.x;
    const int row0 = blockIdx.x * TILE_M;

    #pragma unroll 4
    for (int i = t; i < IN_DIM * OUT_DIM; i += 256) Wsh[i] = W[i];

    for (int i = t; i < TILE_M * (IN_DIM / 4); i += 256) {
        int r  = i / (IN_DIM / 4);
        int k4 = i % (IN_DIM / 4);
        int gr = row0 + r;
        float4 v = (gr < N_NODES) ? ((const float4*)h)[gr * (IN_DIM / 4) + k4]
                                  : make_float4(0.f, 0.f, 0.f, 0.f);
        int p = r >> 1, half = r & 1;
        float* dst = (float*)&hp[p * IN_DIM + k4 * 4];
        dst[0 * 2 + half] = v.x;
        dst[1 * 2 + half] = v.y;
        dst[2 * 2 + half] = v.z;
        dst[3 * 2 + half] = v.w;
    }
    __syncthreads();

    const int c0   = (t & 31) * 2;
    const int pr0  = (t >> 5) * 8;
    const int lane = t & 31;

    ull acc[8][2];
    #pragma unroll
    for (int p = 0; p < 8; p++) { acc[p][0] = 0ULL; acc[p][1] = 0ULL; }

    #pragma unroll 2
    for (int k0 = 0; k0 < IN_DIM; k0 += 2) {
        float2 wA = *(const float2*)&Wsh[k0 * OUT_DIM + c0];
        float2 wB = *(const float2*)&Wsh[(k0 + 1) * OUT_DIM + c0];
        ull b00, b01, b10, b11;
        asm("mov.b64 %0, {%1, %1};" : "=l"(b00) : "r"(__float_as_uint(wA.x)));
        asm("mov.b64 %0, {%1, %1};" : "=l"(b01) : "r"(__float_as_uint(wA.y)));
        asm("mov.b64 %0, {%1, %1};" : "=l"(b10) : "r"(__float_as_uint(wB.x)));
        asm("mov.b64 %0, {%1, %1};" : "=l"(b11) : "r"(__float_as_uint(wB.y)));
        #pragma unroll
        for (int p = 0; p < 8; p++) {
            ulonglong2 vv = *(const ulonglong2*)&hp[(pr0 + p) * IN_DIM + k0];
            asm("fma.rn.f32x2 %0, %1, %2, %0;" : "+l"(acc[p][0]) : "l"(vv.x), "l"(b00));
            asm("fma.rn.f32x2 %0, %1, %2, %0;" : "+l"(acc[p][1]) : "l"(vv.x), "l"(b01));
            asm("fma.rn.f32x2 %0, %1, %2, %0;" : "+l"(acc[p][0]) : "l"(vv.y), "l"(b10));
            asm("fma.rn.f32x2 %0, %1, %2, %0;" : "+l"(acc[p][1]) : "l"(vv.y), "l"(b11));
        }
    }

    // ---- fused s_l / s_r: per-pair partials, butterfly over 32 lanes ----
    const float al0 = __ldg(&a_attn[c0]),      al1 = __ldg(&a_attn[c0 + 1]);
    const float ar0 = __ldg(&a_attn[64 + c0]), ar1 = __ldg(&a_attn[64 + c0 + 1]);
    ull slp[8], srp[8];
    #pragma unroll
    for (int p = 0; p < 8; p++) {
        float2 a0 = *(float2*)&acc[p][0];   // (z[r][c0], z[r+1][c0])
        float2 a1 = *(float2*)&acc[p][1];   // (z[r][c1], z[r+1][c1])
        float2 sl2 = make_float2(a0.x * al0 + a1.x * al1, a0.y * al0 + a1.y * al1);
        float2 sr2 = make_float2(a0.x * ar0 + a1.x * ar1, a0.y * ar0 + a1.y * ar1);
        slp[p] = *(ull*)&sl2;
        srp[p] = *(ull*)&sr2;
    }
    #pragma unroll
    for (int o = 16; o; o >>= 1) {
        #pragma unroll
        for (int p = 0; p < 8; p++) {
            ull ya = __shfl_xor_sync(0xffffffffu, slp[p], o);
            ull yb = __shfl_xor_sync(0xffffffffu, srp[p], o);
            ADD2(slp[p], ya);
            ADD2(srp[p], yb);
        }
    }
    if (lane == 0) {
        #pragma unroll
        for (int p = 0; p < 8; p++) {
            int r0 = row0 + 2 * (pr0 + p);
            float2 sl2 = *(float2*)&slp[p];
            float2 sr2 = *(float2*)&srp[p];
            if (r0 < N_NODES)     { g_sl[r0]     = sl2.x; g_sr[r0]     = sr2.x; }
            if (r0 + 1 < N_NODES) { g_sl[r0 + 1] = sl2.y; g_sr[r0 + 1] = sr2.y; }
        }
    }

    #pragma unroll
    for (int p = 0; p < 8; p++) {
        int r0 = row0 + 2 * (pr0 + p);
        float2 a0 = *(float2*)&acc[p][0];
        float2 a1 = *(float2*)&acc[p][1];
        if (r0 < N_NODES)     *(float2*)&g_z[r0 * OUT_DIM + c0]       = make_float2(a0.x, a1.x);
        if (r0 + 1 < N_NODES) *(float2*)&g_z[(r0 + 1) * OUT_DIM + c0] = make_float2(a0.y, a1.y);
    }
}

// ---------------- zero histogram + denominators ----------------
__global__ void zero_kernel() {
    int i = blockIdx.x * blockDim.x + threadIdx.x;
    if (i <= N_NODES) g_off[i] = 0;
    if (i < N_NODES)  g_den[i] = 0.f;
}

// ---------------- histogram (4 edges/thread) ----------------
__global__ void hist_kernel(const int* __restrict__ edge_dst) {
    int i = blockIdx.x * blockDim.x + threadIdx.x;
    if (i * 4 >= N_EDGES) return;
    int4 d = ((const int4*)edge_dst)[i];
    atomicAdd(&g_off[d.x + 1], 1);
    atomicAdd(&g_off[d.y + 1], 1);
    atomicAdd(&g_off[d.z + 1], 1);
    atomicAdd(&g_off[d.w + 1], 1);
}

// ---------------- thread-coarsened single-block scan ----------------
__global__ void scan_kernel() {
    const int C = 49;
    __shared__ int wsum[32];
    const int t = threadIdx.x, lane = t & 31, w = t >> 5;
    const int base = 1 + t * C;
    int s = 0;
    #pragma unroll
    for (int i = 0; i < C; i++) {
        int idx = base + i;
        s += (idx <= N_NODES) ? g_off[idx] : 0;
    }
    int x = s;
    #pragma unroll
    for (int o = 1; o < 32; o <<= 1) {
        int y = __shfl_up_sync(0xffffffffu, x, o);
        if (lane >= o) x += y;
    }
    if (lane == 31) wsum[w] = x;
    __syncthreads();
    if (w == 0) {
        int v = wsum[lane];
        #pragma unroll
        for (int o = 1; o < 32; o <<= 1) {
            int y = __shfl_up_sync(0xffffffffu, v, o);
            if (lane >= o) v += y;
        }
        wsum[lane] = v;
    }
    __syncthreads();
    int run = x - s + ((w > 0) ? wsum[w - 1] : 0);
    #pragma unroll
    for (int i = 0; i < C; i++) {
        int idx = base + i;
        if (idx <= N_NODES) {
            int cnt = g_off[idx];
            g_cur[idx - 1] = run;
            run += cnt;
            g_off[idx] = run;
        }
    }
}

// ---------------- scatter: 4 edges/thread, packed exp(e)|src + den atomics ----------------
__global__ void scatter_kernel(const int* __restrict__ edge_src,
                               const int* __restrict__ edge_dst) {
    int i = blockIdx.x * blockDim.x + threadIdx.x;
    if (i * 4 >= N_EDGES) return;
    int4 s4 = ((const int4*)edge_src)[i];
    int4 d4 = ((const int4*)edge_dst)[i];
    float e0 = g_sl[s4.x] + g_sr[d4.x];
    float e1 = g_sl[s4.y] + g_sr[d4.y];
    float e2 = g_sl[s4.z] + g_sr[d4.z];
    float e3 = g_sl[s4.w] + g_sr[d4.w];
    e0 = (e0 > 0.f) ? e0 : NEG_SLOPE * e0;
    e1 = (e1 > 0.f) ? e1 : NEG_SLOPE * e1;
    e2 = (e2 > 0.f) ? e2 : NEG_SLOPE * e2;
    e3 = (e3 > 0.f) ? e3 : NEG_SLOPE * e3;
    float x0 = __expf(e0), x1 = __expf(e1), x2 = __expf(e2), x3 = __expf(e3);
    int p0 = atomicAdd(&g_cur[d4.x], 1);
    int p1 = atomicAdd(&g_cur[d4.y], 1);
    int p2 = atomicAdd(&g_cur[d4.z], 1);
    int p3 = atomicAdd(&g_cur[d4.w], 1);
    g_ep[p0] = ((ull)__float_as_uint(x0) << 32) | (unsigned)s4.x;
    g_ep[p1] = ((ull)__float_as_uint(x1) << 32) | (unsigned)s4.y;
    g_ep[p2] = ((ull)__float_as_uint(x2) << 32) | (unsigned)s4.z;
    g_ep[p3] = ((ull)__float_as_uint(x3) << 32) | (unsigned)s4.w;
    atomicAdd(&g_den[d4.x], x0);
    atomicAdd(&g_den[d4.y], x1);
    atomicAdd(&g_den[d4.z], x2);
    atomicAdd(&g_den[d4.w], x3);
}

// ---------------- node phase: one warp per dst, single pass, unroll 4 ----------------
__global__ void node_kernel(float* __restrict__ out) {
    int gw   = (blockIdx.x * blockDim.x + threadIdx.x) >> 5;
    int lane = threadIdx.x & 31;
    if (gw >= N_NODES) return;
    int beg = g_off[gw];
    int end = g_off[gw + 1];

    float2 acc = make_float2(0.f, 0.f);
    if (beg < end) {
        float invden = 1.0f / g_den[gw];
        int j = beg;
        for (; j + 3 < end; j += 4) {
            ull v0 = g_ep[j],     v1 = g_ep[j + 1];
            ull v2 = g_ep[j + 2], v3 = g_ep[j + 3];
            int s0 = (int)(v0 & 0xffffffffu), s1 = (int)(v1 & 0xffffffffu);
            int s2 = (int)(v2 & 0xffffffffu), s3 = (int)(v3 & 0xffffffffu);
            float2 z0 = *(const float2*)&g_z[s0 * OUT_DIM + 2 * lane];
            float2 z1 = *(const float2*)&g_z[s1 * OUT_DIM + 2 * lane];
            float2 z2 = *(const float2*)&g_z[s2 * OUT_DIM + 2 * lane];
            float2 z3 = *(const float2*)&g_z[s3 * OUT_DIM + 2 * lane];
            float a0 = __uint_as_float((uint32_t)(v0 >> 32)) * invden;
            float a1 = __uint_as_float((uint32_t)(v1 >> 32)) * invden;
            float a2 = __uint_as_float((uint32_t)(v2 >> 32)) * invden;
            float a3 = __uint_as_float((uint32_t)(v3 >> 32)) * invden;
            acc.x += a0 * z0.x + a1 * z1.x + a2 * z2.x + a3 * z3.x;
            acc.y += a0 * z0.y + a1 * z1.y + a2 * z2.y + a3 * z3.y;
        }
        for (; j < end; ++j) {
            ull v0 = g_ep[j];
            int s0 = (int)(v0 & 0xffffffffu);
            float a0 = __uint_as_float((uint32_t)(v0 >> 32)) * invden;
            float2 z0 = *(const float2*)&g_z[s0 * OUT_DIM + 2 * lane];
            acc.x += a0 * z0.x;
            acc.y += a0 * z0.y;
        }
    }
    *(float2*)&out[gw * OUT_DIM + 2 * lane] = acc;
}

// ---------------- launch: fork-join two streams inside capture ----------------
extern "C" void kernel_launch(void* const* d_in, const int* in_sizes, int n_in,
                              void* d_out, int out_size) {
    const float* h        = (const float*)d_in[0];
    const int*   edge_src = (const int*)d_in[1];
    const int*   edge_dst = (const int*)d_in[2];
    const float* W_fc     = (const float*)d_in[3];
    const float* a_attn   = (const float*)d_in[4];
    float* out = (float*)d_out;

    static cudaStream_t sB = nullptr;
    static cudaEvent_t  evFork = nullptr, evJoin = nullptr;
    if (!sB) {
        cudaStreamCreateWithFlags(&sB, cudaStreamNonBlocking);
        cudaEventCreateWithFlags(&evFork, cudaEventDisableTiming);
        cudaEventCreateWithFlags(&evJoin, cudaEventDisableTiming);
        const int SMEM = (IN_DIM * OUT_DIM) * 4 + (TILE_M / 2) * IN_DIM * 8;
        cudaFuncSetAttribute(gemm_kernel, cudaFuncAttributeMaxDynamicSharedMemorySize, SMEM);
    }
    const int SMEM = (IN_DIM * OUT_DIM) * 4 + (TILE_M / 2) * IN_DIM * 8; // 192KB

    // fork: stream B handles the edge-dst-only CSR build
    cudaEventRecord(evFork, 0);
    cudaStreamWaitEvent(sB, evFork, 0);

    zero_kernel<<<(N_NODES + 256) / 256, 256, 0, sB>>>();
    hist_kernel<<<(N_EDGES / 4 + 255) / 256, 256, 0, sB>>>(edge_dst);
    scan_kernel<<<1, 1024, 0, sB>>>();
    cudaEventRecord(evJoin, sB);

    // main stream: gemm with fused s_l/s_r
    gemm_kernel<<<(N_NODES + TILE_M - 1) / TILE_M, 256, SMEM>>>(h, W_fc, a_attn);

    // join, then the dependent tail
    cudaStreamWaitEvent(0, evJoin, 0);
    scatter_kernel<<<(N_EDGES / 4 + 255) / 256, 256>>>(edge_src, edge_dst);
    node_kernel<<<(N_NODES * 32 + 255) / 256, 256>>>(out);
}